// round 17
// baseline (speedup 1.0000x reference)
#include <cuda_runtime.h>
#include <cuda_fp16.h>
#include <math.h>
#include <stdint.h>

#define B_    2
#define S_    2048
#define E_    2048
#define H_    16
#define D_    128
#define HALF_ 64
#define MTOT  (B_ * S_)          // 4096
#define N_QKV (3 * E_)           // 6144
#define KDIM  E_                 // 2048
#define BH_   (B_ * H_)          // 32

// ---------------- scratch (__device__ globals; allocation-free) -------------
__device__ float g_qkv[(size_t)MTOT * 3 * E_];
__device__ __half g_x16[(size_t)MTOT * E_];
__device__ __half g_wq16[(size_t)N_QKV * E_];
__device__ __half g_wo16[(size_t)E_ * E_];
__device__ __half g_c16[(size_t)MTOT * E_];
__device__ __half g_Q16[(size_t)BH_ * S_ * D_];
__device__ __half g_K16[(size_t)BH_ * S_ * D_];
__device__ __half g_Vt16[(size_t)BH_ * D_ * S_];

// ---------------- helpers ---------------------------------------------------
__device__ __forceinline__ uint32_t smem_u32(const void* p) {
    uint32_t a;
    asm("{ .reg .u64 t; cvta.to.shared.u64 t, %1; cvt.u32.u64 %0, t; }"
        : "=r"(a) : "l"(p));
    return a;
}

#define CP_ASYNC16(sa, gp) \
    asm volatile("cp.async.cg.shared.global [%0], [%1], 16;" :: "r"(sa), "l"(gp))
#define CP_COMMIT() asm volatile("cp.async.commit_group;" ::: "memory")
#define CP_WAIT(n)  asm volatile("cp.async.wait_group %0;" :: "n"(n) : "memory")

__device__ __forceinline__ void ldsm4(uint32_t& r0, uint32_t& r1, uint32_t& r2,
                                      uint32_t& r3, uint32_t addr) {
    asm volatile("ldmatrix.sync.aligned.m8n8.x4.shared.b16 {%0,%1,%2,%3}, [%4];"
                 : "=r"(r0), "=r"(r1), "=r"(r2), "=r"(r3) : "r"(addr));
}

__device__ __forceinline__ void mma_f16(float* c, const uint32_t* a,
                                        const uint32_t* b) {
    asm volatile(
        "mma.sync.aligned.m16n8k16.row.col.f32.f16.f16.f32 "
        "{%0,%1,%2,%3}, {%4,%5,%6,%7}, {%8,%9}, {%0,%1,%2,%3};"
        : "+f"(c[0]), "+f"(c[1]), "+f"(c[2]), "+f"(c[3])
        : "r"(a[0]), "r"(a[1]), "r"(a[2]), "r"(a[3]), "r"(b[0]), "r"(b[1]));
}

__device__ __forceinline__ uint32_t pack_h2(float f0, float f1) {
    __half2 p = __floats2half2_rn(f0, f1);
    return *reinterpret_cast<uint32_t*>(&p);
}

// ---------------------------------------------------------------------------
// fp32 -> single fp16
// ---------------------------------------------------------------------------
__global__ void __launch_bounds__(256) to_f16(
    const float* __restrict__ in, __half* __restrict__ o16, int n4)
{
    const int i = blockIdx.x * blockDim.x + threadIdx.x;
    if (i >= n4) return;
    const float4 v = reinterpret_cast<const float4*>(in)[i];
    uint2 p;
    p.x = pack_h2(v.x, v.y);
    p.y = pack_h2(v.z, v.w);
    reinterpret_cast<uint2*>(o16)[i] = p;
}

// ---------------------------------------------------------------------------
// HMMA fp16 single-pass GEMM — unchanged from R15 (tensor 58.4%)
// ---------------------------------------------------------------------------
#define RSTRIDE   80
#define TILE_B    (128 * RSTRIDE)
#define STAGE_B   (2 * TILE_B)
#define NSTAGE    4
#define GSM_TOTAL (NSTAGE * STAGE_B)       // 81920

__global__ void __launch_bounds__(128, 2) gemm_hmma_x1(
    const __half* __restrict__ A16, const __half* __restrict__ W16,
    const float* __restrict__ bias, float* __restrict__ C, int N, int K)
{
    extern __shared__ char smem[];
    const uint32_t sb = smem_u32(smem);

    const int tid  = threadIdx.x;
    const int wid  = tid >> 5;
    const int lane = tid & 31;
    const int wm   = wid & 1;
    const int wn   = wid >> 1;
    const int rowBlk = blockIdx.y * 128;
    const int colBlk = blockIdx.x * 128;

    const int gr0 = tid >> 2;
    const int gc  = (tid & 3) * 16;

    auto issue_stage = [&](int k0, int stg) {
        const uint32_t s0 = sb + stg * STAGE_B;
#pragma unroll
        for (int l = 0; l < 4; ++l) {
            const int r = gr0 + l * 32;
            const uint32_t so = r * RSTRIDE + gc;
            CP_ASYNC16(s0 + so,
                       A16 + (size_t)(rowBlk + r) * K + k0 + (gc >> 1));
            CP_ASYNC16(s0 + TILE_B + so,
                       W16 + (size_t)(colBlk + r) * K + k0 + (gc >> 1));
        }
        CP_COMMIT();
    };

    float acc[4][8][4];
#pragma unroll
    for (int i = 0; i < 4; ++i)
#pragma unroll
        for (int j = 0; j < 8; ++j)
#pragma unroll
            for (int q = 0; q < 4; ++q) acc[i][j][q] = 0.0f;

    const uint32_t aOff = (uint32_t)((wm * 64 + (lane & 15)) * RSTRIDE +
                                     (lane >> 4) * 16);
    const uint32_t bOff = (uint32_t)((wn * 64 + (lane & 7) + ((lane >> 4) << 3)) * RSTRIDE +
                                     ((lane >> 3) & 1) * 16);

    const int NCH = K / 32;
    issue_stage(0, 0);
    issue_stage(32, 1);
    issue_stage(64, 2);

    for (int c = 0; c < NCH; ++c) {
        CP_WAIT(2);
        __syncthreads();
        if (c + 3 < NCH) issue_stage((c + 3) * 32, (c + 3) & 3);
        else             CP_COMMIT();

        const uint32_t s0 = sb + (c & 3) * STAGE_B;
        const uint32_t sA = s0 + aOff;
        const uint32_t sW = s0 + TILE_B + bOff;

#pragma unroll
        for (int ks = 0; ks < 2; ++ks) {
            const uint32_t ko = ks * 32;
            uint32_t a[4][4], w[8][2];
#pragma unroll
            for (int mt = 0; mt < 4; ++mt)
                ldsm4(a[mt][0], a[mt][1], a[mt][2], a[mt][3],
                      sA + mt * 16 * RSTRIDE + ko);
#pragma unroll
            for (int p = 0; p < 4; ++p)
                ldsm4(w[2 * p][0], w[2 * p][1], w[2 * p + 1][0], w[2 * p + 1][1],
                      sW + p * 16 * RSTRIDE + ko);
#pragma unroll
            for (int mt = 0; mt < 4; ++mt)
#pragma unroll
                for (int nt = 0; nt < 8; ++nt)
                    mma_f16(acc[mt][nt], a[mt], w[nt]);
        }
    }
    __syncthreads();

    const int g = lane >> 2;
    const int t = lane & 3;
#pragma unroll
    for (int mt = 0; mt < 4; ++mt) {
        const int row0 = rowBlk + wm * 64 + mt * 16 + g;
#pragma unroll
        for (int nt = 0; nt < 8; ++nt) {
            const int col = colBlk + wn * 64 + nt * 8 + 2 * t;
            const float b0 = bias[col], b1 = bias[col + 1];
            float2 v0 = make_float2(acc[mt][nt][0] + b0, acc[mt][nt][1] + b1);
            float2 v1 = make_float2(acc[mt][nt][2] + b0, acc[mt][nt][3] + b1);
            *reinterpret_cast<float2*>(C + (size_t)row0 * N + col) = v0;
            *reinterpret_cast<float2*>(C + (size_t)(row0 + 8) * N + col) = v1;
        }
    }
}

// ---------------------------------------------------------------------------
// Fused rotary + convert: qkv[B,S,3,H,D] fp32 -> Q16, K16 [BH,S,D]
// ---------------------------------------------------------------------------
__global__ void __launch_bounds__(256) qk_rope_cvt(
    const float* __restrict__ qkv,
    __half* __restrict__ Q16, __half* __restrict__ K16)
{
    const int idx = blockIdx.x * blockDim.x + threadIdx.x;
    const int total = B_ * S_ * H_ * HALF_;
    if (idx >= total) return;

    const int dh = idx & (HALF_ - 1);
    const int h  = (idx >> 6) & (H_ - 1);
    const int s  = (idx >> 10) & (S_ - 1);
    const int b  = idx >> 21;

    const double inv = exp(-(double)dh * (log(10000.0) / 64.0));
    const float  f   = (float)((double)s * inv);
    float c, sn;
    sincosf(f, &sn, &c);

    const size_t obase = ((size_t)(b * H_ + h) * S_ + s) * D_;

    {
        const size_t ib = (((size_t)(b * S_ + s) * 3 + 0) * H_ + h) * (size_t)D_;
        const float x1 = qkv[ib + dh], x2 = qkv[ib + dh + HALF_];
        Q16[obase + dh]         = __float2half(x1 * c - x2 * sn);
        Q16[obase + dh + HALF_] = __float2half(x2 * c + x1 * sn);
    }
    {
        const size_t ib = (((size_t)(b * S_ + s) * 3 + 1) * H_ + h) * (size_t)D_;
        const float x1 = qkv[ib + dh], x2 = qkv[ib + dh + HALF_];
        K16[obase + dh]         = __float2half(x1 * c - x2 * sn);
        K16[obase + dh + HALF_] = __float2half(x2 * c + x1 * sn);
    }
}

// ---------------------------------------------------------------------------
// V transpose: qkv comp2 [B,S,H,D] -> Vt16 [BH, D, S]
// ---------------------------------------------------------------------------
__global__ void __launch_bounds__(256) v_transpose(
    const float* __restrict__ qkv, __half* __restrict__ Vt16)
{
    __shared__ float tile[32][33];
    const int tx = threadIdx.x;
    const int ty = threadIdx.y;
    const int s0 = blockIdx.x * 32;
    const int d0 = blockIdx.y * 32;
    const int bh = blockIdx.z;
    const int b  = bh >> 4;
    const int h  = bh & 15;

#pragma unroll
    for (int i = 0; i < 4; ++i) {
        const int s = s0 + ty + i * 8;
        const int d = d0 + tx;
        tile[ty + i * 8][tx] =
            qkv[(((size_t)(b * S_ + s) * 3 + 2) * H_ + h) * (size_t)D_ + d];
    }
    __syncthreads();

#pragma unroll
    for (int i = 0; i < 4; ++i) {
        const int d = d0 + ty + i * 8;
        const int s = s0 + tx;
        Vt16[((size_t)bh * D_ + d) * S_ + s] = __float2half(tile[tx][ty + i * 8]);
    }
}

// ---------------------------------------------------------------------------
// HMMA fp16 flash attention (causal), q-tile 128 (4 warps x m32),
// Q resident in smem, 2-stage KV pipeline, 2 CTAs/SM.
// ---------------------------------------------------------------------------
#define QK_STR 272
#define VT_STR 144
#define ATT_Q   0                               // 128 x 272 = 34816
#define ATT_KV  (128 * QK_STR)                  // 34816
#define ATT_K   0
#define ATT_V   (64 * QK_STR)                   // 17408 within stage
#define ATT_STAGE (64 * QK_STR + 128 * VT_STR)  // 35840
#define ASM_TOTAL (ATT_KV + 2 * ATT_STAGE)      // 106496

__global__ void __launch_bounds__(128, 2) attn_hmma(
    const __half* __restrict__ Q16, const __half* __restrict__ K16,
    const __half* __restrict__ Vt16,
    __half* __restrict__ c16)
{
    extern __shared__ char smem[];
    const uint32_t sb = smem_u32(smem);

    const int qt  = gridDim.x - 1 - blockIdx.x;   // long blocks first; rows [qt*128, +128)
    const int bh  = blockIdx.y;
    const int tid = threadIdx.x;
    const int wq  = tid >> 5;
    const int lane = tid & 31;
    const int g   = lane >> 2;
    const int t   = lane & 3;

    const size_t qkBase = (size_t)bh * S_ * D_;
    const size_t vBase  = (size_t)bh * D_ * S_;

    auto issue_tile = [&](int kt, int stg) {
        const uint32_t k0 = sb + ATT_KV + stg * ATT_STAGE + ATT_K;
        const uint32_t v0 = sb + ATT_KV + stg * ATT_STAGE + ATT_V;
#pragma unroll
        for (int l = 0; l < 8; ++l) {
            const int idx = tid + l * 128;
            {
                const int r = idx >> 4, c = idx & 15;
                CP_ASYNC16(k0 + r * QK_STR + c * 16,
                           K16 + qkBase + (size_t)(kt * 64 + r) * D_ + c * 8);
            }
            {
                const int r = idx >> 3, c = idx & 7;
                CP_ASYNC16(v0 + r * VT_STR + c * 16,
                           Vt16 + vBase + (size_t)r * S_ + kt * 64 + c * 8);
            }
        }
        CP_COMMIT();
    };

    // ---- load Q tile (128x128 f16) into its own smem buffer ----
#pragma unroll
    for (int l = 0; l < 16; ++l) {
        const int idx = tid + l * 128;      // 2048 float4s
        const int r = idx >> 4, c = idx & 15;
        CP_ASYNC16(sb + ATT_Q + r * QK_STR + c * 16,
                   Q16 + qkBase + (size_t)(qt * 128 + r) * D_ + c * 8);
    }
    CP_COMMIT();

    const uint32_t bOffK = (uint32_t)(((lane & 7) + ((lane >> 4) << 3)) * QK_STR +
                                      ((lane >> 3) & 1) * 16);
    const uint32_t bOffV = (uint32_t)(((lane & 7) + ((lane >> 4) << 3)) * VT_STR +
                                      ((lane >> 3) & 1) * 16);
    const uint32_t qOff0 = (uint32_t)((wq * 32 + (lane & 15)) * QK_STR +
                                      (lane >> 4) * 16);   // mt=0; mt=1 adds 16*QK_STR

    float O[2][16][4];
#pragma unroll
    for (int mt = 0; mt < 2; ++mt)
#pragma unroll
        for (int nt = 0; nt < 16; ++nt)
#pragma unroll
            for (int q = 0; q < 4; ++q) O[mt][nt][q] = 0.0f;
    float mx[2][2], ls[2][2];
#pragma unroll
    for (int mt = 0; mt < 2; ++mt) {
        mx[mt][0] = mx[mt][1] = -1e30f;
        ls[mt][0] = ls[mt][1] = 0.0f;
    }

    const float scale = 0.08838834764831843f;
    const int nkt = 2 * qt + 2;

    issue_tile(0, 0);

    for (int kt = 0; kt < nkt; ++kt) {
        const bool more = (kt + 1 < nkt);
        if (more) issue_tile(kt + 1, (kt + 1) & 1);
        if (more) { CP_WAIT(1); } else { CP_WAIT(0); }
        __syncthreads();

        const uint32_t sK = sb + ATT_KV + (kt & 1) * ATT_STAGE + ATT_K;
        const uint32_t sV = sb + ATT_KV + (kt & 1) * ATT_STAGE + ATT_V;

        // ---- S[mt] = Q K^T — kf shared across both m-tiles ----
        float sacc[2][8][4];
#pragma unroll
        for (int mt = 0; mt < 2; ++mt)
#pragma unroll
            for (int nt = 0; nt < 8; ++nt)
#pragma unroll
                for (int q = 0; q < 4; ++q) sacc[mt][nt][q] = 0.0f;

#pragma unroll
        for (int kc = 0; kc < 8; ++kc) {
            uint32_t kf[8][2];
#pragma unroll
            for (int p = 0; p < 4; ++p)
                ldsm4(kf[2 * p][0], kf[2 * p][1], kf[2 * p + 1][0], kf[2 * p + 1][1],
                      sK + p * 16 * QK_STR + bOffK + kc * 32);
            uint32_t qa[2][4];
#pragma unroll
            for (int mt = 0; mt < 2; ++mt)
                ldsm4(qa[mt][0], qa[mt][1], qa[mt][2], qa[mt][3],
                      sb + ATT_Q + qOff0 + mt * 16 * QK_STR + kc * 32);
#pragma unroll
            for (int mt = 0; mt < 2; ++mt)
#pragma unroll
                for (int nt = 0; nt < 8; ++nt)
                    mma_f16(sacc[mt][nt], qa[mt], kf[nt]);
        }

        // ---- scale + causal mask + online softmax (per m-tile) ----
        const bool diag = (kt >= 2 * qt);
        uint32_t pf[2][4][4];
#pragma unroll
        for (int mt = 0; mt < 2; ++mt) {
            const int rg0 = qt * 128 + wq * 32 + mt * 16 + g;   // c0/c1 row
            const int rg1 = rg0 + 8;                            // c2/c3 row
            float rm0 = -1e30f, rm1 = -1e30f;
#pragma unroll
            for (int nt = 0; nt < 8; ++nt) {
                const int cg = kt * 64 + nt * 8 + 2 * t;
                float s0v = sacc[mt][nt][0] * scale;
                float s1v = sacc[mt][nt][1] * scale;
                float s2v = sacc[mt][nt][2] * scale;
                float s3v = sacc[mt][nt][3] * scale;
                if (diag) {
                    if (cg > rg0)     s0v = -1e30f;
                    if (cg + 1 > rg0) s1v = -1e30f;
                    if (cg > rg1)     s2v = -1e30f;
                    if (cg + 1 > rg1) s3v = -1e30f;
                }
                sacc[mt][nt][0] = s0v; sacc[mt][nt][1] = s1v;
                sacc[mt][nt][2] = s2v; sacc[mt][nt][3] = s3v;
                rm0 = fmaxf(rm0, fmaxf(s0v, s1v));
                rm1 = fmaxf(rm1, fmaxf(s2v, s3v));
            }
            rm0 = fmaxf(rm0, __shfl_xor_sync(0xffffffffu, rm0, 1));
            rm0 = fmaxf(rm0, __shfl_xor_sync(0xffffffffu, rm0, 2));
            rm1 = fmaxf(rm1, __shfl_xor_sync(0xffffffffu, rm1, 1));
            rm1 = fmaxf(rm1, __shfl_xor_sync(0xffffffffu, rm1, 2));

            const float mn0 = fmaxf(mx[mt][0], rm0), mn1 = fmaxf(mx[mt][1], rm1);
            const float a0 = __expf(mx[mt][0] - mn0), a1 = __expf(mx[mt][1] - mn1);
            mx[mt][0] = mn0; mx[mt][1] = mn1;

            float rs0 = 0.0f, rs1 = 0.0f;
#pragma unroll
            for (int nt = 0; nt < 8; ++nt) {
                const float p0 = __expf(sacc[mt][nt][0] - mn0);
                const float p1 = __expf(sacc[mt][nt][1] - mn0);
                const float p2 = __expf(sacc[mt][nt][2] - mn1);
                const float p3 = __expf(sacc[mt][nt][3] - mn1);
                sacc[mt][nt][0] = p0; sacc[mt][nt][1] = p1;
                sacc[mt][nt][2] = p2; sacc[mt][nt][3] = p3;
                rs0 += p0 + p1;
                rs1 += p2 + p3;
            }
            rs0 += __shfl_xor_sync(0xffffffffu, rs0, 1);
            rs0 += __shfl_xor_sync(0xffffffffu, rs0, 2);
            rs1 += __shfl_xor_sync(0xffffffffu, rs1, 1);
            rs1 += __shfl_xor_sync(0xffffffffu, rs1, 2);
            ls[mt][0] = ls[mt][0] * a0 + rs0;
            ls[mt][1] = ls[mt][1] * a1 + rs1;

#pragma unroll
            for (int nt = 0; nt < 16; ++nt) {
                O[mt][nt][0] *= a0; O[mt][nt][1] *= a0;
                O[mt][nt][2] *= a1; O[mt][nt][3] *= a1;
            }

            // pack P fragments
#pragma unroll
            for (int kc = 0; kc < 4; ++kc) {
                const int n0 = 2 * kc, n1 = 2 * kc + 1;
                pf[mt][kc][0] = pack_h2(sacc[mt][n0][0], sacc[mt][n0][1]);
                pf[mt][kc][1] = pack_h2(sacc[mt][n0][2], sacc[mt][n0][3]);
                pf[mt][kc][2] = pack_h2(sacc[mt][n1][0], sacc[mt][n1][1]);
                pf[mt][kc][3] = pack_h2(sacc[mt][n1][2], sacc[mt][n1][3]);
            }
        }

        // ---- O += P V — vh shared across both m-tiles ----
#pragma unroll
        for (int kc = 0; kc < 4; ++kc) {
#pragma unroll
            for (int p = 0; p < 8; ++p) {
                uint32_t vh[2][2];
                ldsm4(vh[0][0], vh[0][1], vh[1][0], vh[1][1],
                      sV + p * 16 * VT_STR + bOffV + kc * 32);
#pragma unroll
                for (int mt = 0; mt < 2; ++mt) {
                    mma_f16(O[mt][2 * p],     pf[mt][kc], vh[0]);
                    mma_f16(O[mt][2 * p + 1], pf[mt][kc], vh[1]);
                }
            }
        }
        __syncthreads();   // readers done before this stage is overwritten
    }

    // ---- epilogue ----
    const int b = bh >> 4, h = bh & 15;
#pragma unroll
    for (int mt = 0; mt < 2; ++mt) {
        const float i0 = 1.0f / ls[mt][0], i1 = 1.0f / ls[mt][1];
        const int row0 = qt * 128 + wq * 32 + mt * 16 + g;
#pragma unroll
        for (int nt = 0; nt < 16; ++nt) {
            const int col = h * D_ + nt * 8 + 2 * t;
            const size_t o0 = (size_t)(b * S_ + row0) * E_ + col;
            const size_t o1 = (size_t)(b * S_ + row0 + 8) * E_ + col;
            *reinterpret_cast<uint32_t*>(c16 + o0) =
                pack_h2(O[mt][nt][0] * i0, O[mt][nt][1] * i0);
            *reinterpret_cast<uint32_t*>(c16 + o1) =
                pack_h2(O[mt][nt][2] * i1, O[mt][nt][3] * i1);
        }
    }
}

// ---------------------------------------------------------------------------
extern "C" void kernel_launch(void* const* d_in, const int* in_sizes, int n_in,
                              void* d_out, int out_size)
{
    const float* x    = (const float*)d_in[0];
    const float* wqkv = (const float*)d_in[1];
    const float* bqkv = (const float*)d_in[2];
    const float* wout = (const float*)d_in[3];
    const float* bout = (const float*)d_in[4];
    float* out = (float*)d_out;

    float* qkv;
    __half *x16, *wq16, *wo16, *c16;
    __half *Q16, *K16, *Vt16;
    cudaGetSymbolAddress((void**)&qkv, g_qkv);
    cudaGetSymbolAddress((void**)&x16, g_x16);
    cudaGetSymbolAddress((void**)&wq16, g_wq16);
    cudaGetSymbolAddress((void**)&wo16, g_wo16);
    cudaGetSymbolAddress((void**)&c16, g_c16);
    cudaGetSymbolAddress((void**)&Q16, g_Q16);
    cudaGetSymbolAddress((void**)&K16, g_K16);
    cudaGetSymbolAddress((void**)&Vt16, g_Vt16);

    cudaFuncSetAttribute(gemm_hmma_x1,
                         cudaFuncAttributeMaxDynamicSharedMemorySize, GSM_TOTAL);
    cudaFuncSetAttribute(attn_hmma,
                         cudaFuncAttributeMaxDynamicSharedMemorySize, ASM_TOTAL);

    // 0) converts
    {
        int n4;
        n4 = MTOT * E_ / 4;
        to_f16<<<(n4 + 255) / 256, 256>>>(x, x16, n4);
        n4 = N_QKV * E_ / 4;
        to_f16<<<(n4 + 255) / 256, 256>>>(wqkv, wq16, n4);
        n4 = E_ * E_ / 4;
        to_f16<<<(n4 + 255) / 256, 256>>>(wout, wo16, n4);
    }

    // 1) QKV projection
    gemm_hmma_x1<<<dim3(N_QKV / 128, MTOT / 128), 128, GSM_TOTAL>>>(
        x16, wq16, bqkv, qkv, N_QKV, KDIM);

    // 2) rotary + convert Q,K ; transpose V
    qk_rope_cvt<<<(B_ * S_ * H_ * HALF_ + 255) / 256, 256>>>(qkv, Q16, K16);
    v_transpose<<<dim3(S_ / 32, D_ / 32, BH_), dim3(32, 8)>>>(qkv, Vt16);

    // 3) fp16 flash attention (q-tile 128) -> c16
    attn_hmma<<<dim3(S_ / 128, BH_), 128, ASM_TOTAL>>>(Q16, K16, Vt16, c16);

    // 4) output projection
    gemm_hmma_x1<<<dim3(E_ / 128, MTOT / 128), 128, GSM_TOTAL>>>(
        c16, wo16, bout, out, E_, KDIM);
}